// round 13
// baseline (speedup 1.0000x reference)
#include <cuda_runtime.h>
#include <cstdint>
#include <math.h>

// Problem constants
#define Bq 16
#define Nq 4096
#define Cq 81
#define MAXPC 4096   // capacity per (b,c); also per-image kept capacity (each roi emits <=1)
#define KK 200       // per-class cap and final output count
#define NW 7         // ceil(200/32) words for keep/suppress bitmasks
#define ROWS_PB 128  // rois per argmax block
#define SLOWS 512    // smem sort capacity in per-class slow path
#define FCAP 2048    // finalize candidate capacity after radix cutoff

typedef unsigned long long u64;

// ---------------- device scratch (allocation-free rule: __device__ globals) ----------------
// g_cnt starts zeroed and is re-zeroed by its consumer each run (graph-replay safe).
__device__ int   g_cnt[Bq * Cq];
__device__ float g_cscore[(size_t)Bq * Cq * MAXPC];
__device__ int   g_cidx[(size_t)Bq * Cq * MAXPC];
__device__ float g_kscore[Bq * MAXPC];
__device__ float g_kbox[Bq * MAXPC * 4];
__device__ int   g_ktag[Bq * MAXPC];                 // tag = class*4096 + roi_idx (<2^19)

// ---------------- kernel 1: staged per-roi argmax + emit (R4 version, measured 9.2us) ------
// Softmax: p>0.5 implies argmax; reference emits iff argmax class != 0 and p > 0.5.
__global__ void __launch_bounds__(ROWS_PB) argmax_emit_kernel(const float* __restrict__ probs) {
    __shared__ float srow[ROWS_PB * Cq];   // 41472 B

    int tid = threadIdx.x;
    const float4* __restrict__ src = (const float4*)(probs + (size_t)blockIdx.x * ROWS_PB * Cq);
    float4* dst = (float4*)srow;
    #pragma unroll
    for (int i = 0; i < 20; i++)
        dst[i * ROWS_PB + tid] = src[i * ROWS_PB + tid];
    if (tid < 32) dst[20 * ROWS_PB + tid] = src[20 * ROWS_PB + tid];   // 2592 = 20*128+32
    __syncthreads();

    const float* r = srow + tid * Cq;
    float va = r[0]; int ia = 0;
    #pragma unroll
    for (int k = 1; k <= 40; k++) {
        float pv = r[k];
        if (pv > va) { va = pv; ia = k; }            // strict > keeps lowest index
    }
    float vb = r[41]; int ib = 41;
    #pragma unroll
    for (int k = 42; k < Cq; k++) {
        float pv = r[k];
        if (pv > vb) { vb = pv; ib = k; }
    }
    float v = va; int ix = ia;
    if (vb > va) { v = vb; ix = ib; }

    if (ix != 0 && v > 0.5f) {
        int g = blockIdx.x * ROWS_PB + tid;
        int b = g >> 12, n = g & (Nq - 1);
        int bc = b * Cq + ix;
        int pos = atomicAdd(&g_cnt[bc], 1);
        if (pos < MAXPC) {
            g_cscore[(size_t)bc * MAXPC + pos] = v;
            g_cidx[(size_t)bc * MAXPC + pos]   = n;
        }
    }
}

// ---------------- box decode ----------------
__device__ __forceinline__ void decode_box(const float* __restrict__ roi,
                                           const float* __restrict__ deltas,
                                           int b, int c, int idx,
                                           float& oy1, float& ox1, float& oy2, float& ox2) {
    const float* r = roi + ((size_t)b * Nq + idx) * 4;
    float y1 = r[0], x1 = r[1], y2 = r[2], x2 = r[3];
    float ah = y2 - y1, aw = x2 - x1;
    float acy = y1 + 0.5f * ah, acx = x1 + 0.5f * aw;
    const float* d = deltas + (((size_t)b * Nq + idx) * Cq + c) * 4;
    float dy = d[0] * 0.1f, dx = d[1] * 0.1f;
    float dh = d[2] * 0.2f, dw = d[3] * 0.2f;
    float bh = expf(dh) * ah, bw = expf(dw) * aw;
    float bcy = dy * ah + acy, bcx = dx * aw + acx;
    oy1 = bcy - 0.5f * bh; ox1 = bcx - 0.5f * bw;
    oy2 = oy1 + bh;        ox2 = ox1 + bw;
}

__device__ __forceinline__ unsigned score_dd(unsigned bits) {
    unsigned d = bits - 0x3F000000u;     // (0, 0x800000] for scores in (0.5, 1.0]
    return d > 0x7FFFFFu ? 0x7FFFFFu : d;
}

// ---------------- kernel 2: ONE block per image = all NMS + finalize fused ----------------
// All per-(b,c) candidate sets of image b are consumed by block b; kept results go to
// g_k*[b] (written and read by the SAME block, ordered by __syncthreads). No grid sync.
struct SmemN { u64 skey[SLOWS]; float sbox[KK * 4];
               unsigned smask[KK * NW]; unsigned skeep[NW]; int s_base; };   // ~12.9 KB
struct SmemF { u64 skey[FCAP]; int hist[256]; int s_cnt, s_bsel, s_need2, s_bsel2; }; // ~17.4 KB
union SmemU { SmemN n; SmemF f; };

__global__ void __launch_bounds__(1024) nms_finalize_kernel(const float* __restrict__ roi,
                                                            const float* __restrict__ deltas,
                                                            float* __restrict__ out) {
    __shared__ SmemU sm;
    __shared__ int s_kcnt;                 // kept-candidate count for this image
    __shared__ int s_nbig;
    __shared__ int s_big[Cq];              // classes needing the block-level slow path

    const unsigned FULL = 0xffffffffu;
    int b = blockIdx.x;
    int tid = threadIdx.x;
    int warp = tid >> 5, lane = tid & 31;

    if (tid == 0) { s_kcnt = 0; s_nbig = 0; }
    __syncthreads();

    // =============== PHASE 1: fast classes (M <= 32), one warp per class ===============
    for (int c = warp; c < Cq; c += 32) {
        int bc = b * Cq + c;
        int M = g_cnt[bc];                 // warp-uniform broadcast load
        if (M == 0) continue;
        if (M > 32) {
            if (lane == 0) { int p = atomicAdd(&s_nbig, 1); s_big[p] = c; }
            continue;
        }
        if (lane == 0) g_cnt[bc] = 0;      // reset for next graph replay

        u64 key = 0ull;
        if (lane < M) {
            float sc = g_cscore[(size_t)bc * MAXPC + lane];
            int   idx = g_cidx[(size_t)bc * MAXPC + lane];
            key = ((u64)__float_as_uint(sc) << 32) | (unsigned)(Nq - 1 - idx);
        }
        // in-register bitonic sort, descending (padding keys 0 sink to the end);
        // tie -> lower roi index first (matches lax.top_k stability)
        #pragma unroll
        for (int k = 2; k <= 32; k <<= 1) {
            #pragma unroll
            for (int j = k >> 1; j > 0; j >>= 1) {
                u64 other = __shfl_xor_sync(FULL, key, j);
                bool up = ((lane & j) == 0);
                bool desc = ((lane & k) == 0);
                u64 mx = key > other ? key : other;
                u64 mn = key > other ? other : key;
                key = (desc == up) ? mx : mn;
            }
        }
        int M2 = M;                        // <= 32 <= KK, per-class cap not binding

        float by1 = 0.f, bxx1 = 0.f, by2 = 0.f, bxx2 = 0.f, area = 0.f;
        if (lane < M2) {
            int idx = Nq - 1 - (int)(key & 0xFFFFFFFFull);
            decode_box(roi, deltas, b, c, idx, by1, bxx1, by2, bxx2);
            area = fmaxf(by2 - by1, 0.0f) * fmaxf(bxx2 - bxx1, 0.0f);
        }
        // greedy NMS: shfl-broadcast box i, ballot the suppressions (keep warp-uniform)
        unsigned keep = (M2 >= 32) ? FULL : ((1u << M2) - 1u);
        for (int i = 0; i < M2 - 1; i++) {
            if ((keep >> i) & 1u) {
                float iy1 = __shfl_sync(FULL, by1, i);
                float ix1 = __shfl_sync(FULL, bxx1, i);
                float iy2 = __shfl_sync(FULL, by2, i);
                float ix2 = __shfl_sync(FULL, bxx2, i);
                float ia  = __shfl_sync(FULL, area, i);
                float yy1 = fmaxf(iy1, by1), xx1 = fmaxf(ix1, bxx1);
                float yy2 = fminf(iy2, by2), xx2 = fminf(ix2, bxx2);
                float inter = fmaxf(yy2 - yy1, 0.0f) * fmaxf(xx2 - xx1, 0.0f);
                float iou = inter / (ia + area - inter + 1e-8f);
                unsigned sup = __ballot_sync(FULL,
                    (lane > i) && (lane < M2) && ((keep >> lane) & 1u) && (iou > 0.5f));
                keep &= ~sup;
            }
        }
        int nk = __popc(keep);
        int base = 0;
        if (lane == 0) base = atomicAdd(&s_kcnt, nk);
        base = __shfl_sync(FULL, base, 0);
        if ((lane < M2) && ((keep >> lane) & 1u)) {
            int pos = __popc(keep & ((lane == 0) ? 0u : ((1u << lane) - 1u)));
            int o = base + pos;            // total kept per image <= Nq = MAXPC
            int idx = Nq - 1 - (int)(key & 0xFFFFFFFFull);
            g_kscore[b * MAXPC + o] = __uint_as_float((unsigned)(key >> 32));
            g_ktag[b * MAXPC + o]   = c * Nq + idx;
            g_kbox[(b * MAXPC + o) * 4 + 0] = by1;
            g_kbox[(b * MAXPC + o) * 4 + 1] = bxx1;
            g_kbox[(b * MAXPC + o) * 4 + 2] = by2;
            g_kbox[(b * MAXPC + o) * 4 + 3] = bxx2;
        }
    }
    __syncthreads();

    // =============== PHASE 2: big classes (M > 32), whole block, sequential ===============
    int nbig = s_nbig;
    for (int bi = 0; bi < nbig; bi++) {
        int c = s_big[bi];
        int bc = b * Cq + c;
        int M = g_cnt[bc];
        if (M > MAXPC) M = MAXPC;

        int S = 64;
        while (S < M) S <<= 1;
        bool in_smem = (S <= SLOWS);

        if (in_smem) {
            for (int i = tid; i < S; i += blockDim.x) {
                u64 key = 0ull;
                if (i < M) {
                    float sc = g_cscore[(size_t)bc * MAXPC + i];
                    int   idx = g_cidx[(size_t)bc * MAXPC + i];
                    key = ((u64)__float_as_uint(sc) << 32) | (unsigned)(Nq - 1 - idx);
                }
                sm.n.skey[i] = key;
            }
            __syncthreads();
            if (tid == 0) g_cnt[bc] = 0;
            for (int k = 2; k <= S; k <<= 1)
                for (int j = k >> 1; j > 0; j >>= 1) {
                    for (int i = tid; i < S; i += blockDim.x) {
                        int ixj = i ^ j;
                        if (ixj > i) {
                            u64 a = sm.n.skey[i], bv = sm.n.skey[ixj];
                            bool sw = ((i & k) == 0) ? (a < bv) : (a > bv);
                            if (sw) { sm.n.skey[i] = bv; sm.n.skey[ixj] = a; }
                        }
                    }
                    __syncthreads();
                }
        } else {
            if (tid == 0) g_cnt[bc] = 0;
            for (int i = M + tid; i < S; i += blockDim.x) {
                g_cscore[(size_t)bc * MAXPC + i] = 0.0f;
                g_cidx[(size_t)bc * MAXPC + i]   = Nq - 1;
            }
            __syncthreads();
            for (int k = 2; k <= S; k <<= 1)
                for (int j = k >> 1; j > 0; j >>= 1) {
                    for (int i = tid; i < S; i += blockDim.x) {
                        int ixj = i ^ j;
                        if (ixj > i) {
                            float sa = g_cscore[(size_t)bc * MAXPC + i];
                            float sb = g_cscore[(size_t)bc * MAXPC + ixj];
                            int ida = g_cidx[(size_t)bc * MAXPC + i];
                            int idb = g_cidx[(size_t)bc * MAXPC + ixj];
                            u64 a  = ((u64)__float_as_uint(sa) << 32) | (unsigned)(Nq - 1 - ida);
                            u64 bv = ((u64)__float_as_uint(sb) << 32) | (unsigned)(Nq - 1 - idb);
                            bool sw = ((i & k) == 0) ? (a < bv) : (a > bv);
                            if (sw) {
                                g_cscore[(size_t)bc * MAXPC + i]   = sb;
                                g_cscore[(size_t)bc * MAXPC + ixj] = sa;
                                g_cidx[(size_t)bc * MAXPC + i]     = idb;
                                g_cidx[(size_t)bc * MAXPC + ixj]   = ida;
                            }
                        }
                    }
                    __syncthreads();
                }
        }

        int M2 = (M < KK) ? M : KK;
        for (int t = tid; t < M2 * NW; t += blockDim.x) sm.n.smask[t] = 0u;
        for (int t = tid; t < M2; t += blockDim.x) {
            int idx = in_smem ? (Nq - 1 - (int)(sm.n.skey[t] & 0xFFFFFFFFull))
                              : g_cidx[(size_t)bc * MAXPC + t];
            float oy1, ox1, oy2, ox2;
            decode_box(roi, deltas, b, c, idx, oy1, ox1, oy2, ox2);
            sm.n.sbox[t * 4 + 0] = oy1;
            sm.n.sbox[t * 4 + 1] = ox1;
            sm.n.sbox[t * 4 + 2] = oy2;
            sm.n.sbox[t * 4 + 3] = ox2;
        }
        __syncthreads();

        int npairs = M2 * M2;
        for (int t = tid; t < npairs; t += blockDim.x) {
            int i = t / M2, j = t % M2;
            if (j > i) {
                float iy1 = sm.n.sbox[i * 4 + 0], ix1 = sm.n.sbox[i * 4 + 1];
                float iy2 = sm.n.sbox[i * 4 + 2], ix2 = sm.n.sbox[i * 4 + 3];
                float jy1 = sm.n.sbox[j * 4 + 0], jx1 = sm.n.sbox[j * 4 + 1];
                float jy2 = sm.n.sbox[j * 4 + 2], jx2 = sm.n.sbox[j * 4 + 3];
                float yy1 = fmaxf(iy1, jy1), xx1 = fmaxf(ix1, jx1);
                float yy2 = fminf(iy2, jy2), xx2 = fminf(ix2, jx2);
                float inter = fmaxf(yy2 - yy1, 0.0f) * fmaxf(xx2 - xx1, 0.0f);
                float ia = fmaxf(iy2 - iy1, 0.0f) * fmaxf(ix2 - ix1, 0.0f);
                float ja = fmaxf(jy2 - jy1, 0.0f) * fmaxf(jx2 - jx1, 0.0f);
                float iou = inter / (ia + ja - inter + 1e-8f);
                if (iou > 0.5f)
                    atomicOr(&sm.n.smask[i * NW + (j >> 5)], 1u << (j & 31));
            }
        }
        __syncthreads();

        if (tid < 32) {
            int w = tid;
            unsigned kw = 0u;
            if (w < NW) {
                int lo = w * 32, nb = M2 - lo;
                kw = (nb >= 32) ? 0xFFFFFFFFu : (nb <= 0 ? 0u : ((1u << nb) - 1u));
            }
            for (int i = 0; i < M2; i++) {
                unsigned ow = __shfl_sync(FULL, kw, i >> 5);
                if ((ow >> (i & 31)) & 1u) {
                    if (w < NW) kw &= ~sm.n.smask[i * NW + w];
                }
            }
            if (w < NW) sm.n.skeep[w] = kw;
        }
        __syncthreads();

        if (tid == 0) {
            int nk = 0;
            for (int w = 0; w < NW; w++) nk += __popc(sm.n.skeep[w]);
            sm.n.s_base = atomicAdd(&s_kcnt, nk);
        }
        __syncthreads();
        int base = sm.n.s_base;
        for (int t = tid; t < M2; t += blockDim.x) {
            int tw = t >> 5, tb = t & 31;
            if ((sm.n.skeep[tw] >> tb) & 1u) {
                int pos = 0;
                for (int w = 0; w < tw; w++) pos += __popc(sm.n.skeep[w]);
                pos += __popc(sm.n.skeep[tw] & ((tb == 0) ? 0u : ((1u << tb) - 1u)));
                int o = base + pos;
                int idx; float sc;
                if (in_smem) {
                    u64 key = sm.n.skey[t];
                    idx = Nq - 1 - (int)(key & 0xFFFFFFFFull);
                    sc  = __uint_as_float((unsigned)(key >> 32));
                } else {
                    idx = g_cidx[(size_t)bc * MAXPC + t];
                    sc  = g_cscore[(size_t)bc * MAXPC + t];
                }
                g_kscore[b * MAXPC + o] = sc;
                g_ktag[b * MAXPC + o]   = c * Nq + idx;
                g_kbox[(b * MAXPC + o) * 4 + 0] = sm.n.sbox[t * 4 + 0];
                g_kbox[(b * MAXPC + o) * 4 + 1] = sm.n.sbox[t * 4 + 1];
                g_kbox[(b * MAXPC + o) * 4 + 2] = sm.n.sbox[t * 4 + 2];
                g_kbox[(b * MAXPC + o) * 4 + 3] = sm.n.sbox[t * 4 + 3];
            }
        }
        __syncthreads();
    }

    // =============== PHASE 3: finalize (same block; global writes ordered by barrier) =======
    __syncthreads();
    int Mi = s_kcnt;                              // <= Nq = MAXPC
    int target = Mi < KK ? Mi : KK;

    if (tid < 256) sm.f.hist[tid] = 0;
    if (tid == 0) sm.f.s_cnt = 0;
    __syncthreads();

    // level-1 histogram: top 8 bits of mantissa-delta (scores in (0.5,1.0])
    for (int i = tid; i < Mi; i += blockDim.x) {
        unsigned dd = score_dd(__float_as_uint(g_kscore[b * MAXPC + i]));
        atomicAdd(&sm.f.hist[dd >> 15], 1);
    }
    __syncthreads();

    if (tid == 0) {
        int cum = 0, bsel = 0;
        sm.f.s_need2 = 0;
        for (int bk = 255; bk >= 0; bk--) {
            cum += sm.f.hist[bk];
            if (cum >= target) { bsel = bk; sm.f.s_need2 = target - (cum - sm.f.hist[bk]); break; }
        }
        sm.f.s_bsel = bsel;
    }
    __syncthreads();
    int bsel = sm.f.s_bsel, need2 = sm.f.s_need2;

    // level-2 refine within the cutoff bucket (next 8 mantissa bits)
    if (tid < 256) sm.f.hist[tid] = 0;
    __syncthreads();
    for (int i = tid; i < Mi; i += blockDim.x) {
        unsigned dd = score_dd(__float_as_uint(g_kscore[b * MAXPC + i]));
        if ((int)(dd >> 15) == bsel)
            atomicAdd(&sm.f.hist[(dd >> 7) & 0xFF], 1);
    }
    __syncthreads();

    if (tid == 0) {
        int cum = 0, bsel2 = 0;
        for (int bk = 255; bk >= 0; bk--) {
            cum += sm.f.hist[bk];
            if (cum >= need2) { bsel2 = bk; break; }
        }
        sm.f.s_bsel2 = bsel2;
    }
    __syncthreads();
    int bsel2 = sm.f.s_bsel2;

    // compact keys above the refined cutoff (score desc; tie -> class asc, roi asc via
    // inverted tag; low 12 bits carry the storage slot as payload)
    for (int i = tid; i < Mi; i += blockDim.x) {
        unsigned bits = __float_as_uint(g_kscore[b * MAXPC + i]);
        unsigned dd = score_dd(bits);
        int l1 = (int)(dd >> 15);
        bool take = (l1 > bsel) || (l1 == bsel && (int)((dd >> 7) & 0xFF) >= bsel2);
        if (take) {
            int pos = atomicAdd(&sm.f.s_cnt, 1);
            if (pos < FCAP) {
                int tag = g_ktag[b * MAXPC + i];
                sm.f.skey[pos] = ((u64)bits << 32) |
                                 ((u64)((0xFFFFFu - (unsigned)tag) & 0xFFFFFu) << 12) |
                                 (u64)(unsigned)i;
            }
        }
    }
    __syncthreads();
    int cnt = sm.f.s_cnt < FCAP ? sm.f.s_cnt : FCAP;   // ~target + ties (128-ulp window)

    int S = 0;
    if (cnt > 0) { S = 32; while (S < cnt) S <<= 1; }
    for (int i = cnt + tid; i < S; i += blockDim.x) sm.f.skey[i] = 0ull;
    __syncthreads();

    for (int k = 2; k <= S; k <<= 1) {
        for (int j = k >> 1; j > 0; j >>= 1) {
            for (int i = tid; i < S; i += blockDim.x) {
                int ixj = i ^ j;
                if (ixj > i) {
                    u64 a = sm.f.skey[i], bv = sm.f.skey[ixj];
                    bool sw = ((i & k) == 0) ? (a < bv) : (a > bv);
                    if (sw) { sm.f.skey[i] = bv; sm.f.skey[ixj] = a; }
                }
            }
            __syncthreads();
        }
    }

    // write top-200 (boxes, labels, scores), zero-padding: covers 100% of d_out
    int vlim = cnt < target ? cnt : target;
    for (int t = tid; t < KK; t += blockDim.x) {
        float bx0 = 0.f, bx1 = 0.f, bx2 = 0.f, bx3 = 0.f, lbl = 0.f, scv = 0.f;
        if (t < vlim) {
            u64 key = sm.f.skey[t];
            scv = __uint_as_float((unsigned)(key >> 32));   // always > 0.5 here
            int slot = (int)(key & 0xFFFull);
            int tag = 0xFFFFF - (int)((key >> 12) & 0xFFFFFull);
            lbl = (float)(tag >> 12);                       // tag / 4096 = class
            const float* bp = &g_kbox[(b * MAXPC + slot) * 4];
            bx0 = fminf(fmaxf(bp[0], 0.0f), 1.0f);
            bx1 = fminf(fmaxf(bp[1], 0.0f), 1.0f);
            bx2 = fminf(fmaxf(bp[2], 0.0f), 1.0f);
            bx3 = fminf(fmaxf(bp[3], 0.0f), 1.0f);
        }
        float* ob = out + ((size_t)b * KK + t) * 4;
        ob[0] = bx0; ob[1] = bx1; ob[2] = bx2; ob[3] = bx3;
        out[(size_t)Bq * KK * 4 + (size_t)b * KK + t] = lbl;
        out[(size_t)Bq * KK * 4 + (size_t)Bq * KK + (size_t)b * KK + t] = scv;
    }
}

// ---------------- host launch ----------------
extern "C" void kernel_launch(void* const* d_in, const int* in_sizes, int n_in,
                              void* d_out, int out_size) {
    const float* roi = nullptr;     // B*N*4       = 262144
    const float* deltas = nullptr;  // B*N*C*4     = 21233664
    const float* probs = nullptr;   // B*N*C       = 5308416
    for (int i = 0; i < n_in; i++) {
        if (in_sizes[i] == Bq * Nq * 4)           roi    = (const float*)d_in[i];
        else if (in_sizes[i] == Bq * Nq * Cq * 4) deltas = (const float*)d_in[i];
        else if (in_sizes[i] == Bq * Nq * Cq)     probs  = (const float*)d_in[i];
    }
    float* out = (float*)d_out;

    argmax_emit_kernel<<<(Bq * Nq) / ROWS_PB, ROWS_PB>>>(probs);
    nms_finalize_kernel<<<Bq, 1024>>>(roi, deltas, out);
}

// round 14
// speedup vs baseline: 1.4737x; 1.4737x over previous
#include <cuda_runtime.h>
#include <cstdint>
#include <math.h>

// Problem constants
#define Bq 16
#define Nq 4096
#define Cq 81
#define MAXPC 4096   // capacity per (b,c); also per-image kept capacity (each roi emits <=1)
#define KK 200       // per-class cap and final output count
#define NW 7         // ceil(200/32) words for keep/suppress bitmasks
#define ROWS_PB 128  // rois per argmax block
#define SLOWS 512    // smem sort capacity in per-class slow path
#define FCAP 1024    // finalize smem sort capacity (global-scratch fallback beyond)

typedef unsigned long long u64;

// ---------------- device scratch (allocation-free rule: __device__ globals) ----------------
// Counters start zeroed (static init) and are re-zeroed by their consumers each run.
__device__ int   g_cnt[Bq * Cq];
__device__ float g_cscore[(size_t)Bq * Cq * MAXPC];
__device__ int   g_cidx[(size_t)Bq * Cq * MAXPC];
__device__ int   g_kcnt[Bq];
__device__ float g_kscore[Bq * MAXPC];
__device__ float g_kbox[Bq * MAXPC * 4];
__device__ int   g_ktag[Bq * MAXPC];                 // tag = class*4096 + roi_idx (<2^19)
__device__ int   g_classdone[Bq];                    // last-block-finalizes counter
__device__ u64   g_fscratch[Bq * MAXPC];             // finalize compaction scratch (512 KB)

// ---------------- kernel 1: staged per-roi argmax + emit (R4 version, 9.2us measured) ------
// Softmax: p>0.5 implies argmax; reference emits iff argmax class != 0 and p > 0.5.
__global__ void __launch_bounds__(ROWS_PB) argmax_emit_kernel(const float* __restrict__ probs) {
    __shared__ float srow[ROWS_PB * Cq];   // 41472 B

    int tid = threadIdx.x;
    const float4* __restrict__ src = (const float4*)(probs + (size_t)blockIdx.x * ROWS_PB * Cq);
    float4* dst = (float4*)srow;
    #pragma unroll
    for (int i = 0; i < 20; i++)
        dst[i * ROWS_PB + tid] = src[i * ROWS_PB + tid];
    if (tid < 32) dst[20 * ROWS_PB + tid] = src[20 * ROWS_PB + tid];   // 2592 = 20*128+32
    __syncthreads();

    const float* r = srow + tid * Cq;
    float va = r[0]; int ia = 0;
    #pragma unroll
    for (int k = 1; k <= 40; k++) {
        float pv = r[k];
        if (pv > va) { va = pv; ia = k; }            // strict > keeps lowest index
    }
    float vb = r[41]; int ib = 41;
    #pragma unroll
    for (int k = 42; k < Cq; k++) {
        float pv = r[k];
        if (pv > vb) { vb = pv; ib = k; }
    }
    float v = va; int ix = ia;
    if (vb > va) { v = vb; ix = ib; }

    if (ix != 0 && v > 0.5f) {
        int g = blockIdx.x * ROWS_PB + tid;
        int b = g >> 12, n = g & (Nq - 1);
        int bc = b * Cq + ix;
        int pos = atomicAdd(&g_cnt[bc], 1);
        if (pos < MAXPC) {
            g_cscore[(size_t)bc * MAXPC + pos] = v;
            g_cidx[(size_t)bc * MAXPC + pos]   = n;
        }
    }
}

// ---------------- box decode ----------------
__device__ __forceinline__ void decode_box(const float* __restrict__ roi,
                                           const float* __restrict__ deltas,
                                           int b, int c, int idx,
                                           float& oy1, float& ox1, float& oy2, float& ox2) {
    const float* r = roi + ((size_t)b * Nq + idx) * 4;
    float y1 = r[0], x1 = r[1], y2 = r[2], x2 = r[3];
    float ah = y2 - y1, aw = x2 - x1;
    float acy = y1 + 0.5f * ah, acx = x1 + 0.5f * aw;
    const float* d = deltas + (((size_t)b * Nq + idx) * Cq + c) * 4;
    float dy = d[0] * 0.1f, dx = d[1] * 0.1f;
    float dh = d[2] * 0.2f, dw = d[3] * 0.2f;
    float bh = expf(dh) * ah, bw = expf(dw) * aw;
    float bcy = dy * ah + acy, bcx = dx * aw + acx;
    oy1 = bcy - 0.5f * bh; ox1 = bcx - 0.5f * bw;
    oy2 = oy1 + bh;        ox2 = ox1 + bw;
}

__device__ __forceinline__ unsigned score_dd(unsigned bits) {
    unsigned d = bits - 0x3F000000u;     // (0, 0x800000] for scores in (0.5, 1.0]
    return d > 0x7FFFFFu ? 0x7FFFFFu : d;
}

// ---------------- kernel 2: per-(b,c) NMS + last-block finalize (no 3rd launch) ----------
struct SmemN { u64 skey[SLOWS]; float sbox[KK * 4];
               unsigned smask[KK * NW]; unsigned skeep[NW]; int s_base; };   // ~12.9 KB
struct SmemF { u64 skey[FCAP]; int hist[256]; int s_cnt, s_bsel, s_need2, s_bsel2; }; // ~9.2 KB
union SmemU { SmemN n; SmemF f; };

__global__ void __launch_bounds__(256) nms_kernel(const float* __restrict__ roi,
                                                  const float* __restrict__ deltas,
                                                  float* __restrict__ out) {
    __shared__ SmemU sm;
    __shared__ int s_last, s_Mi;

    const unsigned FULL = 0xffffffffu;
    int bc = blockIdx.x;
    int b = bc / Cq, c = bc % Cq;
    int tid = threadIdx.x;
    int M = g_cnt[bc];                             // all threads read before reset
    if (M > MAXPC) M = MAXPC;

    // ======================= per-class NMS =======================
    if (M > 0 && M <= 32) {
        // ---------- FAST PATH: warp 0 only, register-resident ----------
        if (tid < 32) {
            int lane = tid;
            if (lane == 0) g_cnt[bc] = 0;          // reset for next graph replay

            u64 key = 0ull;
            if (lane < M) {
                float sc = g_cscore[(size_t)bc * MAXPC + lane];
                int   idx = g_cidx[(size_t)bc * MAXPC + lane];
                key = ((u64)__float_as_uint(sc) << 32) | (unsigned)(Nq - 1 - idx);
            }
            // register bitonic sort desc; tie -> lower roi idx (lax.top_k stability)
            #pragma unroll
            for (int k = 2; k <= 32; k <<= 1) {
                #pragma unroll
                for (int j = k >> 1; j > 0; j >>= 1) {
                    u64 other = __shfl_xor_sync(FULL, key, j);
                    bool up = ((lane & j) == 0);
                    bool desc = ((lane & k) == 0);
                    u64 mx = key > other ? key : other;
                    u64 mn = key > other ? other : key;
                    key = (desc == up) ? mx : mn;
                }
            }
            int M2 = M;                            // <= 32 <= KK

            float by1 = 0.f, bxx1 = 0.f, by2 = 0.f, bxx2 = 0.f, area = 0.f;
            if (lane < M2) {
                int idx = Nq - 1 - (int)(key & 0xFFFFFFFFull);
                decode_box(roi, deltas, b, c, idx, by1, bxx1, by2, bxx2);
                area = fmaxf(by2 - by1, 0.0f) * fmaxf(bxx2 - bxx1, 0.0f);
            }
            unsigned keep = (M2 >= 32) ? FULL : ((1u << M2) - 1u);
            for (int i = 0; i < M2 - 1; i++) {
                if ((keep >> i) & 1u) {
                    float iy1 = __shfl_sync(FULL, by1, i);
                    float ix1 = __shfl_sync(FULL, bxx1, i);
                    float iy2 = __shfl_sync(FULL, by2, i);
                    float ix2 = __shfl_sync(FULL, bxx2, i);
                    float ia  = __shfl_sync(FULL, area, i);
                    float yy1 = fmaxf(iy1, by1), xx1 = fmaxf(ix1, bxx1);
                    float yy2 = fminf(iy2, by2), xx2 = fminf(ix2, bxx2);
                    float inter = fmaxf(yy2 - yy1, 0.0f) * fmaxf(xx2 - xx1, 0.0f);
                    float iou = inter / (ia + area - inter + 1e-8f);
                    unsigned sup = __ballot_sync(FULL,
                        (lane > i) && (lane < M2) && ((keep >> lane) & 1u) && (iou > 0.5f));
                    keep &= ~sup;
                }
            }
            int nk = __popc(keep);
            int base = 0;
            if (lane == 0) base = atomicAdd(&g_kcnt[b], nk);
            base = __shfl_sync(FULL, base, 0);
            if ((lane < M2) && ((keep >> lane) & 1u)) {
                int pos = __popc(keep & ((lane == 0) ? 0u : ((1u << lane) - 1u)));
                int o = base + pos;
                int idx = Nq - 1 - (int)(key & 0xFFFFFFFFull);
                g_kscore[b * MAXPC + o] = __uint_as_float((unsigned)(key >> 32));
                g_ktag[b * MAXPC + o]   = c * Nq + idx;
                g_kbox[(b * MAXPC + o) * 4 + 0] = by1;
                g_kbox[(b * MAXPC + o) * 4 + 1] = bxx1;
                g_kbox[(b * MAXPC + o) * 4 + 2] = by2;
                g_kbox[(b * MAXPC + o) * 4 + 3] = bxx2;
            }
        }
    } else if (M > 32) {
        // ---------- SLOW PATH: block-level sort + bitmask NMS (rare) ----------
        if (tid == 0) g_cnt[bc] = 0;               // reset (count only; data still used)
        int S = 64;
        while (S < M) S <<= 1;
        bool in_smem = (S <= SLOWS);

        if (in_smem) {
            for (int i = tid; i < S; i += blockDim.x) {
                u64 key = 0ull;
                if (i < M) {
                    float sc = g_cscore[(size_t)bc * MAXPC + i];
                    int   idx = g_cidx[(size_t)bc * MAXPC + i];
                    key = ((u64)__float_as_uint(sc) << 32) | (unsigned)(Nq - 1 - idx);
                }
                sm.n.skey[i] = key;
            }
            __syncthreads();
            for (int k = 2; k <= S; k <<= 1)
                for (int j = k >> 1; j > 0; j >>= 1) {
                    for (int i = tid; i < S; i += blockDim.x) {
                        int ixj = i ^ j;
                        if (ixj > i) {
                            u64 a = sm.n.skey[i], bv = sm.n.skey[ixj];
                            bool sw = ((i & k) == 0) ? (a < bv) : (a > bv);
                            if (sw) { sm.n.skey[i] = bv; sm.n.skey[ixj] = a; }
                        }
                    }
                    __syncthreads();
                }
        } else {
            for (int i = M + tid; i < S; i += blockDim.x) {
                g_cscore[(size_t)bc * MAXPC + i] = 0.0f;
                g_cidx[(size_t)bc * MAXPC + i]   = Nq - 1;
            }
            __syncthreads(); __threadfence_block();
            for (int k = 2; k <= S; k <<= 1)
                for (int j = k >> 1; j > 0; j >>= 1) {
                    for (int i = tid; i < S; i += blockDim.x) {
                        int ixj = i ^ j;
                        if (ixj > i) {
                            float sa = g_cscore[(size_t)bc * MAXPC + i];
                            float sb = g_cscore[(size_t)bc * MAXPC + ixj];
                            int ida = g_cidx[(size_t)bc * MAXPC + i];
                            int idb = g_cidx[(size_t)bc * MAXPC + ixj];
                            u64 a  = ((u64)__float_as_uint(sa) << 32) | (unsigned)(Nq - 1 - ida);
                            u64 bv = ((u64)__float_as_uint(sb) << 32) | (unsigned)(Nq - 1 - idb);
                            bool sw = ((i & k) == 0) ? (a < bv) : (a > bv);
                            if (sw) {
                                g_cscore[(size_t)bc * MAXPC + i]   = sb;
                                g_cscore[(size_t)bc * MAXPC + ixj] = sa;
                                g_cidx[(size_t)bc * MAXPC + i]     = idb;
                                g_cidx[(size_t)bc * MAXPC + ixj]   = ida;
                            }
                        }
                    }
                    __syncthreads(); __threadfence_block();
                }
        }

        int M2 = (M < KK) ? M : KK;                // reference per-class top-K cap
        for (int t = tid; t < M2 * NW; t += blockDim.x) sm.n.smask[t] = 0u;
        for (int t = tid; t < M2; t += blockDim.x) {
            int idx = in_smem ? (Nq - 1 - (int)(sm.n.skey[t] & 0xFFFFFFFFull))
                              : g_cidx[(size_t)bc * MAXPC + t];
            float oy1, ox1, oy2, ox2;
            decode_box(roi, deltas, b, c, idx, oy1, ox1, oy2, ox2);
            sm.n.sbox[t * 4 + 0] = oy1;
            sm.n.sbox[t * 4 + 1] = ox1;
            sm.n.sbox[t * 4 + 2] = oy2;
            sm.n.sbox[t * 4 + 3] = ox2;
        }
        __syncthreads();

        int npairs = M2 * M2;
        for (int t = tid; t < npairs; t += blockDim.x) {
            int i = t / M2, j = t % M2;
            if (j > i) {
                float iy1 = sm.n.sbox[i * 4 + 0], ix1 = sm.n.sbox[i * 4 + 1];
                float iy2 = sm.n.sbox[i * 4 + 2], ix2 = sm.n.sbox[i * 4 + 3];
                float jy1 = sm.n.sbox[j * 4 + 0], jx1 = sm.n.sbox[j * 4 + 1];
                float jy2 = sm.n.sbox[j * 4 + 2], jx2 = sm.n.sbox[j * 4 + 3];
                float yy1 = fmaxf(iy1, jy1), xx1 = fmaxf(ix1, jx1);
                float yy2 = fminf(iy2, jy2), xx2 = fminf(ix2, jx2);
                float inter = fmaxf(yy2 - yy1, 0.0f) * fmaxf(xx2 - xx1, 0.0f);
                float ia = fmaxf(iy2 - iy1, 0.0f) * fmaxf(ix2 - ix1, 0.0f);
                float ja = fmaxf(jy2 - jy1, 0.0f) * fmaxf(jx2 - jx1, 0.0f);
                float iou = inter / (ia + ja - inter + 1e-8f);
                if (iou > 0.5f)
                    atomicOr(&sm.n.smask[i * NW + (j >> 5)], 1u << (j & 31));
            }
        }
        __syncthreads();

        if (tid < 32) {
            int w = tid;
            unsigned kw = 0u;
            if (w < NW) {
                int lo = w * 32, nb = M2 - lo;
                kw = (nb >= 32) ? 0xFFFFFFFFu : (nb <= 0 ? 0u : ((1u << nb) - 1u));
            }
            for (int i = 0; i < M2; i++) {
                unsigned ow = __shfl_sync(FULL, kw, i >> 5);
                if ((ow >> (i & 31)) & 1u) {
                    if (w < NW) kw &= ~sm.n.smask[i * NW + w];
                }
            }
            if (w < NW) sm.n.skeep[w] = kw;
        }
        __syncthreads();

        if (tid == 0) {
            int nk = 0;
            for (int w = 0; w < NW; w++) nk += __popc(sm.n.skeep[w]);
            sm.n.s_base = atomicAdd(&g_kcnt[b], nk);
        }
        __syncthreads();
        int base = sm.n.s_base;
        for (int t = tid; t < M2; t += blockDim.x) {
            int tw = t >> 5, tb = t & 31;
            if ((sm.n.skeep[tw] >> tb) & 1u) {
                int pos = 0;
                for (int w = 0; w < tw; w++) pos += __popc(sm.n.skeep[w]);
                pos += __popc(sm.n.skeep[tw] & ((tb == 0) ? 0u : ((1u << tb) - 1u)));
                int o = base + pos;
                int idx; float sc;
                if (in_smem) {
                    u64 key = sm.n.skey[t];
                    idx = Nq - 1 - (int)(key & 0xFFFFFFFFull);
                    sc  = __uint_as_float((unsigned)(key >> 32));
                } else {
                    idx = g_cidx[(size_t)bc * MAXPC + t];
                    sc  = g_cscore[(size_t)bc * MAXPC + t];
                }
                g_kscore[b * MAXPC + o] = sc;
                g_ktag[b * MAXPC + o]   = c * Nq + idx;
                g_kbox[(b * MAXPC + o) * 4 + 0] = sm.n.sbox[t * 4 + 0];
                g_kbox[(b * MAXPC + o) * 4 + 1] = sm.n.sbox[t * 4 + 1];
                g_kbox[(b * MAXPC + o) * 4 + 2] = sm.n.sbox[t * 4 + 2];
                g_kbox[(b * MAXPC + o) * 4 + 3] = sm.n.sbox[t * 4 + 3];
            }
        }
    }

    // ============== publish + elect the finalizer (threadFenceReduction pattern) ==============
    __threadfence();                               // all writers publish device-wide
    __syncthreads();
    if (tid == 0)
        s_last = (atomicAdd(&g_classdone[b], 1) == Cq - 1) ? 1 : 0;
    __syncthreads();
    if (!s_last) return;

    // ======================= FINALIZE (this block saw all 81 classes done) =======================
    if (tid == 0) {
        g_classdone[b] = 0;                        // reset for next graph replay
        s_Mi = atomicExch(&g_kcnt[b], 0);          // read + reset kept count
    }
    __threadfence();                               // acquire side
    __syncthreads();
    int Mi = s_Mi;
    if (Mi > MAXPC) Mi = MAXPC;
    int target = Mi < KK ? Mi : KK;

    for (int i = tid; i < 256; i += blockDim.x) sm.f.hist[i] = 0;
    if (tid == 0) sm.f.s_cnt = 0;
    __syncthreads();

    // level-1 histogram: top 8 bits of mantissa-delta (scores in (0.5,1.0])
    for (int i = tid; i < Mi; i += blockDim.x) {
        unsigned dd = score_dd(__float_as_uint(g_kscore[b * MAXPC + i]));
        atomicAdd(&sm.f.hist[dd >> 15], 1);
    }
    __syncthreads();

    if (tid == 0) {
        int cum = 0, bsel = 0;
        sm.f.s_need2 = 0;
        for (int bk = 255; bk >= 0; bk--) {
            cum += sm.f.hist[bk];
            if (cum >= target) { bsel = bk; sm.f.s_need2 = target - (cum - sm.f.hist[bk]); break; }
        }
        sm.f.s_bsel = bsel;
    }
    __syncthreads();
    int bsel = sm.f.s_bsel, need2 = sm.f.s_need2;

    // level-2 refine within the cutoff bucket (next 8 mantissa bits)
    for (int i = tid; i < 256; i += blockDim.x) sm.f.hist[i] = 0;
    __syncthreads();
    for (int i = tid; i < Mi; i += blockDim.x) {
        unsigned dd = score_dd(__float_as_uint(g_kscore[b * MAXPC + i]));
        if ((int)(dd >> 15) == bsel)
            atomicAdd(&sm.f.hist[(dd >> 7) & 0xFF], 1);
    }
    __syncthreads();

    if (tid == 0) {
        int cum = 0, bsel2 = 0;
        for (int bk = 255; bk >= 0; bk--) {
            cum += sm.f.hist[bk];
            if (cum >= need2) { bsel2 = bk; break; }
        }
        sm.f.s_bsel2 = bsel2;
    }
    __syncthreads();
    int bsel2 = sm.f.s_bsel2;

    // compact keys above the refined cutoff into GLOBAL scratch (score desc; tie -> class
    // asc, roi asc via inverted tag; low 12 bits carry the storage slot as payload)
    for (int i = tid; i < Mi; i += blockDim.x) {
        unsigned bits = __float_as_uint(g_kscore[b * MAXPC + i]);
        unsigned dd = score_dd(bits);
        int l1 = (int)(dd >> 15);
        bool take = (l1 > bsel) || (l1 == bsel && (int)((dd >> 7) & 0xFF) >= bsel2);
        if (take) {
            int pos = atomicAdd(&sm.f.s_cnt, 1);
            int tag = g_ktag[b * MAXPC + i];
            g_fscratch[b * MAXPC + pos] =
                ((u64)bits << 32) |
                ((u64)((0xFFFFFu - (unsigned)tag) & 0xFFFFFu) << 12) |
                (u64)(unsigned)i;
        }
    }
    __syncthreads();
    int cnt = sm.f.s_cnt;                          // >= target by construction; ~target + ties

    int S = 0;
    if (cnt > 0) { S = 32; while (S < cnt) S <<= 1; }
    bool fin_smem = (S <= FCAP);

    if (fin_smem) {
        for (int i = tid; i < S; i += blockDim.x)
            sm.f.skey[i] = (i < cnt) ? g_fscratch[b * MAXPC + i] : 0ull;
        __syncthreads();
        for (int k = 2; k <= S; k <<= 1)
            for (int j = k >> 1; j > 0; j >>= 1) {
                for (int i = tid; i < S; i += blockDim.x) {
                    int ixj = i ^ j;
                    if (ixj > i) {
                        u64 a = sm.f.skey[i], bv = sm.f.skey[ixj];
                        bool sw = ((i & k) == 0) ? (a < bv) : (a > bv);
                        if (sw) { sm.f.skey[i] = bv; sm.f.skey[ixj] = a; }
                    }
                }
                __syncthreads();
            }
    } else {
        // rare: massive score ties — sort in global scratch (exactness preserved)
        for (int i = cnt + tid; i < S; i += blockDim.x) g_fscratch[b * MAXPC + i] = 0ull;
        __syncthreads(); __threadfence_block();
        for (int k = 2; k <= S; k <<= 1)
            for (int j = k >> 1; j > 0; j >>= 1) {
                for (int i = tid; i < S; i += blockDim.x) {
                    int ixj = i ^ j;
                    if (ixj > i) {
                        u64 a = g_fscratch[b * MAXPC + i], bv = g_fscratch[b * MAXPC + ixj];
                        bool sw = ((i & k) == 0) ? (a < bv) : (a > bv);
                        if (sw) { g_fscratch[b * MAXPC + i] = bv; g_fscratch[b * MAXPC + ixj] = a; }
                    }
                }
                __syncthreads(); __threadfence_block();
            }
    }

    // write top-200 (boxes, labels, scores), zero-padding: covers 100% of d_out
    int vlim = cnt < target ? cnt : target;
    for (int t = tid; t < KK; t += blockDim.x) {
        float bx0 = 0.f, bx1 = 0.f, bx2 = 0.f, bx3 = 0.f, lbl = 0.f, scv = 0.f;
        if (t < vlim) {
            u64 key = fin_smem ? sm.f.skey[t] : g_fscratch[b * MAXPC + t];
            scv = __uint_as_float((unsigned)(key >> 32));   // always > 0.5 here
            int slot = (int)(key & 0xFFFull);
            int tag = 0xFFFFF - (int)((key >> 12) & 0xFFFFFull);
            lbl = (float)(tag >> 12);                       // tag / 4096 = class
            const float* bp = &g_kbox[(b * MAXPC + slot) * 4];
            bx0 = fminf(fmaxf(bp[0], 0.0f), 1.0f);
            bx1 = fminf(fmaxf(bp[1], 0.0f), 1.0f);
            bx2 = fminf(fmaxf(bp[2], 0.0f), 1.0f);
            bx3 = fminf(fmaxf(bp[3], 0.0f), 1.0f);
        }
        float* ob = out + ((size_t)b * KK + t) * 4;
        ob[0] = bx0; ob[1] = bx1; ob[2] = bx2; ob[3] = bx3;
        out[(size_t)Bq * KK * 4 + (size_t)b * KK + t] = lbl;
        out[(size_t)Bq * KK * 4 + (size_t)Bq * KK + (size_t)b * KK + t] = scv;
    }
}

// ---------------- host launch ----------------
extern "C" void kernel_launch(void* const* d_in, const int* in_sizes, int n_in,
                              void* d_out, int out_size) {
    const float* roi = nullptr;     // B*N*4       = 262144
    const float* deltas = nullptr;  // B*N*C*4     = 21233664
    const float* probs = nullptr;   // B*N*C       = 5308416
    for (int i = 0; i < n_in; i++) {
        if (in_sizes[i] == Bq * Nq * 4)           roi    = (const float*)d_in[i];
        else if (in_sizes[i] == Bq * Nq * Cq * 4) deltas = (const float*)d_in[i];
        else if (in_sizes[i] == Bq * Nq * Cq)     probs  = (const float*)d_in[i];
    }
    float* out = (float*)d_out;

    argmax_emit_kernel<<<(Bq * Nq) / ROWS_PB, ROWS_PB>>>(probs);
    nms_kernel<<<Bq * Cq, 256>>>(roi, deltas, out);
}

// round 15
// speedup vs baseline: 1.5514x; 1.0527x over previous
#include <cuda_runtime.h>
#include <cstdint>
#include <math.h>

// Problem constants
#define Bq 16
#define Nq 4096
#define Cq 81
#define MAXPC 4096   // capacity per (b,c); also per-image kept capacity
#define KK 200       // per-class cap and final output count
#define NW 7         // ceil(200/32) words for keep/suppress bitmasks
#define ROWS_PB 128  // rois per argmax block
#define SLOWS 512    // smem sort capacity in per-class slow path
#define FCAP 2048    // finalize smem sort capacity

typedef unsigned long long u64;

// ---------------- device scratch (allocation-free rule: __device__ globals) ----------------
// Counters start zeroed (static init) and are re-zeroed by their consumers each run.
__device__ int    g_cnt[Bq * Cq];
__device__ float  g_cscore[(size_t)Bq * Cq * MAXPC];
__device__ int    g_cidx[(size_t)Bq * Cq * MAXPC];
__device__ float4 g_cbox[Bq * Nq];                   // decoded box per roi (unique class/roi)
__device__ int    g_kcnt[Bq];
__device__ float  g_kscore[Bq * MAXPC];
__device__ float  g_kbox[Bq * MAXPC * 4];
__device__ int    g_ktag[Bq * MAXPC];                // tag = class*4096 + roi_idx (<2^19)

// ---------------- kernel 1: staged argmax + emit + BOX DECODE AT EMISSION ----------------
// Softmax: p>0.5 implies argmax; reference emits iff argmax class != 0 and p > 0.5.
// The emitting thread also decodes the candidate's box (each roi emits at most one
// candidate, for exactly one class), so downstream kernels never touch roi/deltas.
__global__ void __launch_bounds__(ROWS_PB) argmax_emit_kernel(const float* __restrict__ probs,
                                                              const float* __restrict__ roi,
                                                              const float* __restrict__ deltas) {
    __shared__ float srow[ROWS_PB * Cq];   // 41472 B

    int tid = threadIdx.x;
    const float4* __restrict__ src = (const float4*)(probs + (size_t)blockIdx.x * ROWS_PB * Cq);
    float4* dst = (float4*)srow;
    #pragma unroll
    for (int i = 0; i < 20; i++)
        dst[i * ROWS_PB + tid] = src[i * ROWS_PB + tid];
    if (tid < 32) dst[20 * ROWS_PB + tid] = src[20 * ROWS_PB + tid];   // 2592 = 20*128+32
    __syncthreads();

    const float* r = srow + tid * Cq;
    float va = r[0]; int ia = 0;
    #pragma unroll
    for (int k = 1; k <= 40; k++) {
        float pv = r[k];
        if (pv > va) { va = pv; ia = k; }            // strict > keeps lowest index
    }
    float vb = r[41]; int ib = 41;
    #pragma unroll
    for (int k = 42; k < Cq; k++) {
        float pv = r[k];
        if (pv > vb) { vb = pv; ib = k; }
    }
    float v = va; int ix = ia;
    if (vb > va) { v = vb; ix = ib; }

    if (ix != 0 && v > 0.5f) {
        int g = blockIdx.x * ROWS_PB + tid;
        int b = g >> 12, n = g & (Nq - 1);
        int bc = b * Cq + ix;
        int pos = atomicAdd(&g_cnt[bc], 1);
        if (pos < MAXPC) {
            g_cscore[(size_t)bc * MAXPC + pos] = v;
            g_cidx[(size_t)bc * MAXPC + pos]   = n;
        }
        // decode the box now (rare: ~0.4% of threads)
        const float* rr = roi + (size_t)g * 4;
        float y1 = rr[0], x1 = rr[1], y2 = rr[2], x2 = rr[3];
        float ah = y2 - y1, aw = x2 - x1;
        float acy = y1 + 0.5f * ah, acx = x1 + 0.5f * aw;
        const float* d = deltas + ((size_t)g * Cq + ix) * 4;
        float dy = d[0] * 0.1f, dx = d[1] * 0.1f;
        float dh = d[2] * 0.2f, dw = d[3] * 0.2f;
        float bh = expf(dh) * ah, bw = expf(dw) * aw;
        float bcy = dy * ah + acy, bcx = dx * aw + acx;
        float oy1 = bcy - 0.5f * bh, ox1 = bcx - 0.5f * bw;
        g_cbox[g] = make_float4(oy1, ox1, oy1 + bh, ox1 + bw);
    }
}

// ---------------- kernel 2: per-(b,c) sort + NMS (gather-free fast path) ----------------
__global__ void __launch_bounds__(128) per_class_nms_kernel() {
    __shared__ u64 skey[SLOWS];                    // 4 KB (slow path only)
    __shared__ float sbox[KK * 4];                 // 3.2 KB
    __shared__ unsigned smask[KK * NW];            // 5.6 KB
    __shared__ unsigned skeep[NW];
    __shared__ int   s_base;

    const unsigned FULL = 0xffffffffu;
    int bc = blockIdx.x;
    int b = bc / Cq, c = bc % Cq;
    int tid = threadIdx.x;
    int M = g_cnt[bc];                             // all threads read before reset
    if (M > MAXPC) M = MAXPC;
    if (M == 0) return;

    // =============== FAST PATH: M <= 32, warp 0, zero gathers after sort ===============
    if (M <= 32) {
        if (tid >= 32) return;
        int lane = tid;
        if (lane == 0) g_cnt[bc] = 0;              // reset for next graph replay

        // key: score desc | roi-idx asc (bits 8..19) | source lane (bits 0..7).
        // roi idx is unique per (b,c), so the slot bits never influence ordering.
        u64 key = 0ull;
        float4 box = make_float4(0.f, 0.f, 0.f, 0.f);
        if (lane < M) {
            float sc = g_cscore[(size_t)bc * MAXPC + lane];
            int   idx = g_cidx[(size_t)bc * MAXPC + lane];
            key = ((u64)__float_as_uint(sc) << 32) |
                  ((u64)(unsigned)(Nq - 1 - idx) << 8) | (unsigned)lane;
            box = g_cbox[b * Nq + idx];            // parallel with the key chain
        }
        // in-register bitonic sort, descending (padding keys 0 sink to the end)
        #pragma unroll
        for (int k = 2; k <= 32; k <<= 1) {
            #pragma unroll
            for (int j = k >> 1; j > 0; j >>= 1) {
                u64 other = __shfl_xor_sync(FULL, key, j);
                bool up = ((lane & j) == 0);
                bool desc = ((lane & k) == 0);
                u64 mx = key > other ? key : other;
                u64 mn = key > other ? other : key;
                key = (desc == up) ? mx : mn;
            }
        }
        int M2 = M;                                // <= 32 <= KK

        // permute boxes to sorted order via shfl (no post-sort gather)
        int srcl = (int)(key & 0xFFull);
        float by1  = __shfl_sync(FULL, box.x, srcl);
        float bxx1 = __shfl_sync(FULL, box.y, srcl);
        float by2  = __shfl_sync(FULL, box.z, srcl);
        float bxx2 = __shfl_sync(FULL, box.w, srcl);
        float area = (lane < M2) ? fmaxf(by2 - by1, 0.0f) * fmaxf(bxx2 - bxx1, 0.0f) : 0.0f;

        // greedy NMS: shfl-broadcast box i, ballot suppressions (keep warp-uniform)
        unsigned keep = (M2 >= 32) ? FULL : ((1u << M2) - 1u);
        for (int i = 0; i < M2 - 1; i++) {
            if ((keep >> i) & 1u) {
                float iy1 = __shfl_sync(FULL, by1, i);
                float ix1 = __shfl_sync(FULL, bxx1, i);
                float iy2 = __shfl_sync(FULL, by2, i);
                float ix2 = __shfl_sync(FULL, bxx2, i);
                float ia  = __shfl_sync(FULL, area, i);
                float yy1 = fmaxf(iy1, by1), xx1 = fmaxf(ix1, bxx1);
                float yy2 = fminf(iy2, by2), xx2 = fminf(ix2, bxx2);
                float inter = fmaxf(yy2 - yy1, 0.0f) * fmaxf(xx2 - xx1, 0.0f);
                float iou = inter / (ia + area - inter + 1e-8f);
                unsigned sup = __ballot_sync(FULL,
                    (lane > i) && (lane < M2) && ((keep >> lane) & 1u) && (iou > 0.5f));
                keep &= ~sup;
            }
        }
        int nk = __popc(keep);
        int base = 0;
        if (lane == 0) base = atomicAdd(&g_kcnt[b], nk);
        base = __shfl_sync(FULL, base, 0);
        if ((lane < M2) && ((keep >> lane) & 1u)) {
            int pos = __popc(keep & ((lane == 0) ? 0u : ((1u << lane) - 1u)));
            int o = base + pos;
            int idx = Nq - 1 - (int)((key >> 8) & 0xFFFull);
            g_kscore[b * MAXPC + o] = __uint_as_float((unsigned)(key >> 32));
            g_ktag[b * MAXPC + o]   = c * Nq + idx;
            g_kbox[(b * MAXPC + o) * 4 + 0] = by1;
            g_kbox[(b * MAXPC + o) * 4 + 1] = bxx1;
            g_kbox[(b * MAXPC + o) * 4 + 2] = by2;
            g_kbox[(b * MAXPC + o) * 4 + 3] = bxx2;
        }
        return;
    }

    // =============== SLOW PATH: M > 32 (rare); boxes read from g_cbox (no expf) ===============
    int S = 64;
    while (S < M) S <<= 1;
    bool in_smem = (S <= SLOWS);

    if (in_smem) {
        for (int i = tid; i < S; i += blockDim.x) {
            u64 key = 0ull;
            if (i < M) {
                float sc = g_cscore[(size_t)bc * MAXPC + i];
                int   idx = g_cidx[(size_t)bc * MAXPC + i];
                key = ((u64)__float_as_uint(sc) << 32) | (unsigned)(Nq - 1 - idx);
            }
            skey[i] = key;
        }
        __syncthreads();
        if (tid == 0) g_cnt[bc] = 0;
        for (int k = 2; k <= S; k <<= 1)
            for (int j = k >> 1; j > 0; j >>= 1) {
                for (int i = tid; i < S; i += blockDim.x) {
                    int ixj = i ^ j;
                    if (ixj > i) {
                        u64 a = skey[i], bv = skey[ixj];
                        bool sw = ((i & k) == 0) ? (a < bv) : (a > bv);
                        if (sw) { skey[i] = bv; skey[ixj] = a; }
                    }
                }
                __syncthreads();
            }
    } else {
        if (tid == 0) g_cnt[bc] = 0;
        for (int i = M + tid; i < S; i += blockDim.x) {
            g_cscore[(size_t)bc * MAXPC + i] = 0.0f;
            g_cidx[(size_t)bc * MAXPC + i]   = Nq - 1;
        }
        __syncthreads(); __threadfence_block();
        for (int k = 2; k <= S; k <<= 1)
            for (int j = k >> 1; j > 0; j >>= 1) {
                for (int i = tid; i < S; i += blockDim.x) {
                    int ixj = i ^ j;
                    if (ixj > i) {
                        float sa = g_cscore[(size_t)bc * MAXPC + i];
                        float sb = g_cscore[(size_t)bc * MAXPC + ixj];
                        int ida = g_cidx[(size_t)bc * MAXPC + i];
                        int idb = g_cidx[(size_t)bc * MAXPC + ixj];
                        u64 a  = ((u64)__float_as_uint(sa) << 32) | (unsigned)(Nq - 1 - ida);
                        u64 bv = ((u64)__float_as_uint(sb) << 32) | (unsigned)(Nq - 1 - idb);
                        bool sw = ((i & k) == 0) ? (a < bv) : (a > bv);
                        if (sw) {
                            g_cscore[(size_t)bc * MAXPC + i]   = sb;
                            g_cscore[(size_t)bc * MAXPC + ixj] = sa;
                            g_cidx[(size_t)bc * MAXPC + i]     = idb;
                            g_cidx[(size_t)bc * MAXPC + ixj]   = ida;
                        }
                    }
                }
                __syncthreads(); __threadfence_block();
            }
    }

    int M2 = (M < KK) ? M : KK;                    // reference per-class top-K cap

    for (int t = tid; t < M2 * NW; t += blockDim.x) smask[t] = 0u;
    for (int t = tid; t < M2; t += blockDim.x) {
        int idx = in_smem ? (Nq - 1 - (int)(skey[t] & 0xFFFFFFFFull))
                          : g_cidx[(size_t)bc * MAXPC + t];
        float4 bx = g_cbox[b * Nq + idx];
        sbox[t * 4 + 0] = bx.x;
        sbox[t * 4 + 1] = bx.y;
        sbox[t * 4 + 2] = bx.z;
        sbox[t * 4 + 3] = bx.w;
    }
    __syncthreads();

    int npairs = M2 * M2;
    for (int t = tid; t < npairs; t += blockDim.x) {
        int i = t / M2, j = t % M2;
        if (j > i) {
            float iy1 = sbox[i * 4 + 0], ix1 = sbox[i * 4 + 1];
            float iy2 = sbox[i * 4 + 2], ix2 = sbox[i * 4 + 3];
            float jy1 = sbox[j * 4 + 0], jx1 = sbox[j * 4 + 1];
            float jy2 = sbox[j * 4 + 2], jx2 = sbox[j * 4 + 3];
            float yy1 = fmaxf(iy1, jy1), xx1 = fmaxf(ix1, jx1);
            float yy2 = fminf(iy2, jy2), xx2 = fminf(ix2, jx2);
            float inter = fmaxf(yy2 - yy1, 0.0f) * fmaxf(xx2 - xx1, 0.0f);
            float ia = fmaxf(iy2 - iy1, 0.0f) * fmaxf(ix2 - ix1, 0.0f);
            float ja = fmaxf(jy2 - jy1, 0.0f) * fmaxf(jx2 - jx1, 0.0f);
            float iou = inter / (ia + ja - inter + 1e-8f);
            if (iou > 0.5f)
                atomicOr(&smask[i * NW + (j >> 5)], 1u << (j & 31));
        }
    }
    __syncthreads();

    if (tid < 32) {
        int w = tid;
        unsigned kw = 0u;
        if (w < NW) {
            int lo = w * 32, nb = M2 - lo;
            kw = (nb >= 32) ? 0xFFFFFFFFu : (nb <= 0 ? 0u : ((1u << nb) - 1u));
        }
        for (int i = 0; i < M2; i++) {
            unsigned ow = __shfl_sync(FULL, kw, i >> 5);
            if ((ow >> (i & 31)) & 1u) {
                if (w < NW) kw &= ~smask[i * NW + w];
            }
        }
        if (w < NW) skeep[w] = kw;
    }
    __syncthreads();

    if (tid == 0) {
        int nk = 0;
        for (int w = 0; w < NW; w++) nk += __popc(skeep[w]);
        s_base = atomicAdd(&g_kcnt[b], nk);
    }
    __syncthreads();
    int base = s_base;
    for (int t = tid; t < M2; t += blockDim.x) {
        int tw = t >> 5, tb = t & 31;
        if ((skeep[tw] >> tb) & 1u) {
            int pos = 0;
            for (int w = 0; w < tw; w++) pos += __popc(skeep[w]);
            pos += __popc(skeep[tw] & ((tb == 0) ? 0u : ((1u << tb) - 1u)));
            int o = base + pos;
            int idx; float sc;
            if (in_smem) {
                u64 key = skey[t];
                idx = Nq - 1 - (int)(key & 0xFFFFFFFFull);
                sc  = __uint_as_float((unsigned)(key >> 32));
            } else {
                idx = g_cidx[(size_t)bc * MAXPC + t];
                sc  = g_cscore[(size_t)bc * MAXPC + t];
            }
            g_kscore[b * MAXPC + o] = sc;
            g_ktag[b * MAXPC + o]   = c * Nq + idx;
            g_kbox[(b * MAXPC + o) * 4 + 0] = sbox[t * 4 + 0];
            g_kbox[(b * MAXPC + o) * 4 + 1] = sbox[t * 4 + 1];
            g_kbox[(b * MAXPC + o) * 4 + 2] = sbox[t * 4 + 2];
            g_kbox[(b * MAXPC + o) * 4 + 3] = sbox[t * 4 + 3];
        }
    }
}

// ---------------- kernel 3: per-image top-200 via two-level radix select + tiny sort -------
__device__ __forceinline__ unsigned score_dd(unsigned bits) {
    unsigned d = bits - 0x3F000000u;     // (0, 0x800000] for scores in (0.5, 1.0]
    return d > 0x7FFFFFu ? 0x7FFFFFu : d;
}

__global__ void __launch_bounds__(1024) finalize_kernel(float* __restrict__ out) {
    __shared__ u64 skey[FCAP];   // 16 KB
    __shared__ int hist[256];
    __shared__ int s_cnt, s_bsel, s_need2, s_bsel2;

    int b = blockIdx.x;
    int tid = threadIdx.x;
    int Mi = g_kcnt[b];
    if (Mi > MAXPC) Mi = MAXPC;
    int target = Mi < KK ? Mi : KK;

    if (tid < 256) hist[tid] = 0;
    if (tid == 0) { s_cnt = 0; g_kcnt[b] = 0; }    // reset for next graph replay
    __syncthreads();

    // level-1 histogram: top 8 bits of mantissa-delta
    for (int i = tid; i < Mi; i += blockDim.x) {
        unsigned dd = score_dd(__float_as_uint(g_kscore[b * MAXPC + i]));
        atomicAdd(&hist[dd >> 15], 1);
    }
    __syncthreads();

    if (tid == 0) {
        int cum = 0, bsel = 0;
        s_need2 = 0;
        for (int bk = 255; bk >= 0; bk--) {
            cum += hist[bk];
            if (cum >= target) { bsel = bk; s_need2 = target - (cum - hist[bk]); break; }
        }
        s_bsel = bsel;
    }
    __syncthreads();
    int bsel = s_bsel, need2 = s_need2;

    // level-2 refine within the cutoff bucket (next 8 mantissa bits)
    if (tid < 256) hist[tid] = 0;
    __syncthreads();
    for (int i = tid; i < Mi; i += blockDim.x) {
        unsigned dd = score_dd(__float_as_uint(g_kscore[b * MAXPC + i]));
        if ((int)(dd >> 15) == bsel)
            atomicAdd(&hist[(dd >> 7) & 0xFF], 1);
    }
    __syncthreads();

    if (tid == 0) {
        int cum = 0, bsel2 = 0;
        for (int bk = 255; bk >= 0; bk--) {
            cum += hist[bk];
            if (cum >= need2) { bsel2 = bk; break; }
        }
        s_bsel2 = bsel2;
    }
    __syncthreads();
    int bsel2 = s_bsel2;

    // compact keys above the refined cutoff (score desc; tie -> class asc, roi asc via
    // inverted tag; low 12 bits carry the storage slot as payload)
    for (int i = tid; i < Mi; i += blockDim.x) {
        unsigned bits = __float_as_uint(g_kscore[b * MAXPC + i]);
        unsigned dd = score_dd(bits);
        int l1 = (int)(dd >> 15);
        bool take = (l1 > bsel) || (l1 == bsel && (int)((dd >> 7) & 0xFF) >= bsel2);
        if (take) {
            int pos = atomicAdd(&s_cnt, 1);
            if (pos < FCAP) {
                int tag = g_ktag[b * MAXPC + i];
                skey[pos] = ((u64)bits << 32) |
                            ((u64)((0xFFFFFu - (unsigned)tag) & 0xFFFFFu) << 12) |
                            (u64)(unsigned)i;
            }
        }
    }
    __syncthreads();
    int cnt = s_cnt < FCAP ? s_cnt : FCAP;         // ~target + ties (128-ulp window)

    int S = 0;
    if (cnt > 0) { S = 32; while (S < cnt) S <<= 1; }
    for (int i = cnt + tid; i < S; i += blockDim.x) skey[i] = 0ull;
    __syncthreads();

    for (int k = 2; k <= S; k <<= 1) {
        for (int j = k >> 1; j > 0; j >>= 1) {
            for (int i = tid; i < S; i += blockDim.x) {
                int ixj = i ^ j;
                if (ixj > i) {
                    u64 a = skey[i], bv = skey[ixj];
                    bool sw = ((i & k) == 0) ? (a < bv) : (a > bv);
                    if (sw) { skey[i] = bv; skey[ixj] = a; }
                }
            }
            __syncthreads();
        }
    }

    // write top-200 (boxes, labels, scores), zero-padding: covers 100% of d_out
    int vlim = cnt < target ? cnt : target;
    for (int t = tid; t < KK; t += blockDim.x) {
        float bx0 = 0.f, bx1 = 0.f, bx2 = 0.f, bx3 = 0.f, lbl = 0.f, scv = 0.f;
        if (t < vlim) {
            u64 key = skey[t];
            scv = __uint_as_float((unsigned)(key >> 32));   // always > 0.5 here
            int slot = (int)(key & 0xFFFull);
            int tag = 0xFFFFF - (int)((key >> 12) & 0xFFFFFull);
            lbl = (float)(tag >> 12);                       // tag / 4096 = class
            const float* bp = &g_kbox[(b * MAXPC + slot) * 4];
            bx0 = fminf(fmaxf(bp[0], 0.0f), 1.0f);
            bx1 = fminf(fmaxf(bp[1], 0.0f), 1.0f);
            bx2 = fminf(fmaxf(bp[2], 0.0f), 1.0f);
            bx3 = fminf(fmaxf(bp[3], 0.0f), 1.0f);
        }
        float* ob = out + ((size_t)b * KK + t) * 4;
        ob[0] = bx0; ob[1] = bx1; ob[2] = bx2; ob[3] = bx3;
        out[(size_t)Bq * KK * 4 + (size_t)b * KK + t] = lbl;
        out[(size_t)Bq * KK * 4 + (size_t)Bq * KK + (size_t)b * KK + t] = scv;
    }
}

// ---------------- host launch ----------------
extern "C" void kernel_launch(void* const* d_in, const int* in_sizes, int n_in,
                              void* d_out, int out_size) {
    const float* roi = nullptr;     // B*N*4       = 262144
    const float* deltas = nullptr;  // B*N*C*4     = 21233664
    const float* probs = nullptr;   // B*N*C       = 5308416
    for (int i = 0; i < n_in; i++) {
        if (in_sizes[i] == Bq * Nq * 4)           roi    = (const float*)d_in[i];
        else if (in_sizes[i] == Bq * Nq * Cq * 4) deltas = (const float*)d_in[i];
        else if (in_sizes[i] == Bq * Nq * Cq)     probs  = (const float*)d_in[i];
    }
    float* out = (float*)d_out;

    argmax_emit_kernel<<<(Bq * Nq) / ROWS_PB, ROWS_PB>>>(probs, roi, deltas);
    per_class_nms_kernel<<<Bq * Cq, 128>>>();
    finalize_kernel<<<Bq, 1024>>>(out);
}